// round 10
// baseline (speedup 1.0000x reference)
#include <cuda_runtime.h>

#define BB 32
#define FF 35
#define SS 80
#define NC (2*FF+1)          // 71
#define NPAIR (BB*FF)        // 1120 chains
#define NW (NPAIR/2)         // 560 warps (2 chains per warp, packed f32x2)
#define LN2F 0.69314718055994530942f

typedef unsigned long long u64;

__device__ float g_loss[NPAIR];
__device__ unsigned g_count = 0;

__device__ __forceinline__ u64 pk2(float x, float y) {
    u64 r; asm("mov.b64 %0, {%1,%2};" : "=l"(r) : "f"(x), "f"(y)); return r;
}
__device__ __forceinline__ void up2(u64 v, float& x, float& y) {
    asm("mov.b64 {%0,%1}, %2;" : "=f"(x), "=f"(y) : "l"(v));
}
__device__ __forceinline__ u64 add2(u64 a, u64 b) {
    u64 r; asm("add.rn.f32x2 %0, %1, %2;" : "=l"(r) : "l"(a), "l"(b)); return r;
}
__device__ __forceinline__ u64 mul2(u64 a, u64 b) {
    u64 r; asm("mul.rn.f32x2 %0, %1, %2;" : "=l"(r) : "l"(a), "l"(b)); return r;
}
__device__ __forceinline__ u64 fma2_(u64 a, u64 b, u64 c) {
    u64 r; asm("fma.rn.f32x2 %0, %1, %2, %3;" : "=l"(r) : "l"(a), "l"(b), "l"(c)); return r;
}
__device__ __forceinline__ float frcp(float x) {
    float r; asm("rcp.approx.f32 %0, %1;" : "=f"(r) : "f"(x)); return r;
}
__device__ __forceinline__ u64 shup1(u64 v) {
    // 64-bit shfl_up by 1 (two 32-bit shfls)
    unsigned lo = (unsigned)v, hi = (unsigned)(v >> 32);
    lo = __shfl_up_sync(0xffffffffu, lo, 1);
    hi = __shfl_up_sync(0xffffffffu, hi, 1);
    return ((u64)hi << 32) | lo;
}

// mantissa-normalize into [1,2), accumulate exponent
#define EXTR(Z, ez) { int _bt = __float_as_int(Z); ez += (_bt >> 23) - 127; \
                      Z = __int_as_float((_bt & 0x7fffff) | 0x3f800000); }

__global__ __launch_bounds__(128, 1)
void ctc_fwd(const float* __restrict__ logits,
             const int*   __restrict__ targets,
             const int*   __restrict__ in_len,
             const int*   __restrict__ tgt_len,
             int T, float* __restrict__ out)
{
    __shared__ ulonglong2 sEE[4][32];   // per step: (e0'A,e0'B), (pd'A,pd'B)
    __shared__ float      sred[128];
    __shared__ int        sflag;

    const unsigned FM = 0xffffffffu;
    const int widb = threadIdx.x >> 5;
    const int lane = threadIdx.x & 31;
    const int gw = blockIdx.x * 4 + widb;      // 0..559

    const int cA = gw * 2, cB = cA + 1;
    const int bA = cA / FF, fA = cA - bA * FF;
    const int bB = cB / FF, fB = cB - bB * FF;
    const int tlA = tgt_len[cA], tlB = tgt_len[cB];
    const int LvA = 2 * tlA + 1, LvB = 2 * tlB + 1;
    int TinA = in_len[bA]; if (TinA > T) TinA = T;
    int TinB = in_len[bB]; if (TinB > T) TinB = T;
    const int Tmin = (TinA < TinB) ? TinA : TinB;
    const int Tmax = (TinA > TinB) ? TinA : TinB;

    const int l0 = lane * 6;
    const int* tgA = targets + (size_t)cA * SS;
    const int* tgB = targets + (size_t)cB * SS;

    u64 M[6], W[3], SK[3];
    #pragma unroll
    for (int j = 0; j < 6; j++)
        M[j] = pk2((l0 + j < LvA) ? 1.f : 0.f, (l0 + j < LvB) ? 1.f : 0.f);
    #pragma unroll
    for (int j = 0; j < 3; j++) {
        int l = l0 + 2 * j + 1;
        float wa = 0.f, ska = 0.f, wb = 0.f, skb = 0.f;
        if (l < LvA) { int s = (l - 1) >> 1; int tv = tgA[s];
            wa = (float)tv; ska = (l >= 3 && tgA[s - 1] != tv) ? 1.f : 0.f; }
        if (l < LvB) { int s = (l - 1) >> 1; int tv = tgB[s];
            wb = (float)tv; skb = (l >= 3 && tgB[s - 1] != tv) ? 1.f : 0.f; }
        W[j] = pk2(wa, wb); SK[j] = pk2(ska, skb);
    }

    // prev-lane statics for the shadow a5p recomputation
    u64 W5p  = shup1(W[2]);
    u64 SK5p = shup1(SK[2]);
    u64 M3p  = shup1(M[3]);
    u64 M4p  = shup1(M[4]);
    u64 M5p  = shup1(M[5]);
    u64 LZMP = (lane == 0) ? 0ull : pk2(1.f, 1.f);
    if (lane == 0) { W5p = 0; SK5p = 0; M3p = 0; M4p = 0; M5p = 0; }

    const float* pA = logits + (size_t)bA * NC + fA;
    const float* pB = logits + (size_t)bB * NC + fB;
    const int oblA = 2 * FF - fA;
    const int oblB = 2 * FF - fB;
    const int TS = BB * NC;

    u64 A0 = 0, A1 = 0, A2 = 0, A3 = 0, A4 = 0, A5 = 0;
    u64 a5p = 0, a3p = 0, a4p = 0;    // shadows of prev lane's A5, A3, A4
    float ZaccA = 1.f, ZaccB = 1.f, PaccA = 1.f, PaccB = 1.f;
    int ezA = 0, ezB = 0, epA = 0, epB = 0, EA = 0, EB = 0;

    // ---- t = 0 init (full emissions; Z(0) into lane-0 accumulator) ----
    {
        float e0a = __expf(pA[0]), e1a = __expf(pA[FF]), e2a = __expf(pA[oblA]);
        float e0b = __expf(pB[0]), e1b = __expf(pB[FF]), e2b = __expf(pB[oblB]);
        if (lane == 0) {
            A0 = pk2(e2a, e2b);
            A1 = mul2(fma2_(W[0], pk2(e1a - e0a, e1b - e0b), pk2(e0a, e0b)), M[1]);
            ZaccA = e0a + e1a + e2a;
            ZaccB = e0b + e1b + e2b;
        }
    }

    // ---- prefetch first block (t = 1 + lane) ----
    float rpA = 0.f, rnA = 0.f, rbA = 0.f, rpB = 0.f, rnB = 0.f, rbB = 0.f;
    {
        int tt = 1 + lane;
        if (tt < Tmax) {
            const float* qa = pA + (size_t)tt * TS;
            rpA = qa[0]; rnA = qa[FF]; rbA = qa[oblA];
            const float* qb = pB + (size_t)tt * TS;
            rpB = qb[0]; rnB = qb[FF]; rbB = qb[oblB];
        }
    }

// one CTC step on blank-factored emissions; shadow a5p recomputed locally so
// no SHFL sits on the loop-carried chain. The n3/n4 shuffles issued here are
// consumed only at the END of the next step (in a5n) -> ~one step of slack.
#define STEP_EP(ep) { \
    u64 t1  = fma2_(W[0], ep.y, ep.x); \
    u64 t3  = fma2_(W[1], ep.y, ep.x); \
    u64 t5  = fma2_(W[2], ep.y, ep.x); \
    u64 t5p = fma2_(W5p,  ep.y, ep.x); \
    u64 n0 = add2(A0, a5p); \
    u64 n1 = mul2(fma2_(SK[0], a5p, add2(A1, A0)), t1); \
    u64 n2 = add2(A2, A1); \
    u64 n3 = mul2(fma2_(SK[1], A1, add2(A3, A2)), t3); \
    u64 n4 = add2(A4, A3); \
    u64 n5 = mul2(fma2_(SK[2], A3, add2(A5, A4)), t5); \
    u64 a5n = mul2(fma2_(SK5p, a3p, fma2_(LZMP, a4p, a5p)), t5p); \
    a3p = shup1(n3); \
    a4p = shup1(n4); \
    A0 = n0; A1 = n1; A2 = n2; A3 = n3; A4 = n4; A5 = n5; \
    a5p = a5n; }

// exact power-of-2 rescale; masks zero junk states (numerical containment);
// shadows scaled+masked with prev-lane masks (keeps lane-0 shadow at 0)
#define APPLY(sv) { \
    float sa, sb; up2(sv, sa, sb); \
    int exa = (__float_as_int(sa) >> 23) & 0xff; \
    int exb = (__float_as_int(sb) >> 23) & 0xff; \
    exa = min(max(exa, 1), 253); exb = min(max(exb, 1), 253); \
    EA += exa - 127; EB += exb - 127; \
    u64 sc = pk2(__int_as_float((254 - exa) << 23), __int_as_float((254 - exb) << 23)); \
    A0 = mul2(A0, mul2(sc, M[0])); A1 = mul2(A1, mul2(sc, M[1])); \
    A2 = mul2(A2, mul2(sc, M[2])); A3 = mul2(A3, mul2(sc, M[3])); \
    A4 = mul2(A4, mul2(sc, M[4])); A5 = mul2(A5, mul2(sc, M[5])); \
    a5p = mul2(a5p, mul2(sc, M5p)); \
    a3p = mul2(a3p, mul2(sc, M3p)); \
    a4p = mul2(a4p, mul2(sc, M4p)); }

    for (int tb = 1; tb < Tmax; tb += 32) {
        int ns = Tmax - tb; if (ns > 32) ns = 32;

        // ---- stage blank-factored emissions; accumulate Z and blank product P ----
        float e0a = __expf(rpA), e1a = __expf(rnA), e2a = __expf(rbA);
        float e0b = __expf(rpB), e1b = __expf(rnB), e2b = __expf(rbB);
        float r2a = frcp(e2a), r2b = frcp(e2b);
        __syncwarp();
        sEE[widb][lane] = make_ulonglong2(pk2(e0a * r2a, e0b * r2b),
                                          pk2((e1a - e0a) * r2a, (e1b - e0b) * r2b));
        int tt = tb + lane;
        if (tt < TinA) { ZaccA *= (e0a + e1a + e2a); EXTR(ZaccA, ezA);
                         PaccA *= e2a;               EXTR(PaccA, epA); }
        if (tt < TinB) { ZaccB *= (e0b + e1b + e2b); EXTR(ZaccB, ezB);
                         PaccB *= e2b;               EXTR(PaccB, epB); }

        // prefetch next block
        int tn = tb + 32 + lane;
        if (tn < Tmax) {
            const float* qa = pA + (size_t)tn * TS;
            rpA = qa[0]; rnA = qa[FF]; rbA = qa[oblA];
            const float* qb = pB + (size_t)tn * TS;
            rpB = qb[0]; rnB = qb[FF]; rbB = qb[oblB];
        }
        __syncwarp();

        if (tb + 32 <= Tmin) {
            // fast path: LDS pipelined one step ahead;
            // rescale every 16 steps, butterfly spread over steps 11..15 / 27..31
            u64 sv = 0;
            ulonglong2 ep = sEE[widb][0];
            #pragma unroll
            for (int i = 0; i < 32; i++) {
                ulonglong2 epn;
                if (i < 31) epn = sEE[widb][i + 1];
                STEP_EP(ep);
                if (i < 31) ep = epn;
                if (i == 10 || i == 26)
                    sv = add2(add2(add2(A0, A1), add2(A2, A3)), add2(A4, A5));
                if (i == 11 || i == 27) sv = add2(sv, __shfl_xor_sync(FM, sv, 1));
                if (i == 12 || i == 28) sv = add2(sv, __shfl_xor_sync(FM, sv, 2));
                if (i == 13 || i == 29) sv = add2(sv, __shfl_xor_sync(FM, sv, 4));
                if (i == 14 || i == 30) sv = add2(sv, __shfl_xor_sync(FM, sv, 8));
                if (i == 15 || i == 31) {
                    sv = add2(sv, __shfl_xor_sync(FM, sv, 16));
                    APPLY(sv);
                }
            }
        } else {
            // tail / unequal-length path: per-chain freeze beyond Tin,
            // shadows refreshed by direct shuffles of the frozen state
            for (int i = 0; i < ns; i++) {
                int t = tb + i;
                u64 o0 = A0, o1 = A1, o2 = A2, o3 = A3, o4 = A4, o5 = A5;
                ulonglong2 ep = sEE[widb][i];
                STEP_EP(ep);
                bool ga = (t < TinA), gb = (t < TinB);
                if (!(ga && gb)) {
                    float nx, ny, ox, oy;
                    #define SELST(N, O) { up2(N, nx, ny); up2(O, ox, oy); \
                        N = pk2(ga ? nx : ox, gb ? ny : oy); }
                    SELST(A0, o0) SELST(A1, o1) SELST(A2, o2)
                    SELST(A3, o3) SELST(A4, o4) SELST(A5, o5)
                    #undef SELST
                }
                // refresh shadows from actual registers (cheap; rare path)
                a5p = shup1(A5); if (lane == 0) a5p = 0ull;
                a3p = shup1(A3);     // lane-0 garbage killed by SK5p=0
                a4p = shup1(A4);     // lane-0 garbage killed by LZMP=0
                if ((i & 7) == 7) {
                    u64 sv = add2(add2(add2(A0, A1), add2(A2, A3)), add2(A4, A5));
                    #pragma unroll
                    for (int o = 16; o; o >>= 1)
                        sv = add2(sv, __shfl_xor_sync(FM, sv, o));
                    APPLY(sv);
                }
            }
        }
    }

    // ---- final gather: alpha[2*tl] + alpha[2*tl-1] per chain ----
    float lastA = 0.f, prvA = 0.f, lastB = 0.f, prvB = 0.f;
    {
        int ilA = 2 * tlA, ilB = 2 * tlB;
        float x, y;
        #define GATH(j, R) { up2(R, x, y); int l = l0 + j; \
            if (l == ilA) lastA = x; if (l == ilA - 1) prvA = x; \
            if (l == ilB) lastB = y; if (l == ilB - 1) prvB = y; }
        GATH(0, A0) GATH(1, A1) GATH(2, A2) GATH(3, A3) GATH(4, A4) GATH(5, A5)
        #undef GATH
    }
    u64 fs = pk2(lastA + prvA, lastB + prvB);
    u64 lz = pk2(__logf(ZaccA) - __logf(PaccA) + (float)(ezA - epA) * LN2F,
                 __logf(ZaccB) - __logf(PaccB) + (float)(ezB - epB) * LN2F);
    #pragma unroll
    for (int o = 16; o; o >>= 1) {
        fs = add2(fs, __shfl_xor_sync(FM, fs, o));
        lz = add2(lz, __shfl_xor_sync(FM, lz, o));
    }
    if (lane == 0) {
        float sa, sb, za, zb;
        up2(fs, sa, sb); up2(lz, za, zb);
        float lossA = 0.f, lossB = 0.f;
        if (sa > 0.f) lossA = za - (__logf(sa) + (float)EA * LN2F);
        if (sb > 0.f) lossB = zb - (__logf(sb) + (float)EB * LN2F);
        g_loss[cA] = lossA / fmaxf((float)tlA, 1.f);
        g_loss[cB] = lossB / fmaxf((float)tlB, 1.f);
    }

    // ---- fused grid reduction ----
    __syncthreads();
    if (threadIdx.x == 0) {
        __threadfence();
        unsigned v = atomicAdd(&g_count, 1u);
        sflag = (v == gridDim.x - 1u) ? 1 : 0;
    }
    __syncthreads();
    if (sflag) {
        __threadfence();
        float acc = 0.f;
        for (int i = threadIdx.x; i < NPAIR; i += 128) acc += g_loss[i];
        sred[threadIdx.x] = acc;
        __syncthreads();
        #pragma unroll
        for (int o = 64; o; o >>= 1) {
            if (threadIdx.x < o) sred[threadIdx.x] += sred[threadIdx.x + o];
            __syncthreads();
        }
        if (threadIdx.x == 0) {
            out[0] = sred[0] * (1.0f / (float)BB);
            g_count = 0;
            __threadfence();
        }
    }
}

extern "C" void kernel_launch(void* const* d_in, const int* in_sizes, int n_in,
                              void* d_out, int out_size)
{
    const float* logits  = (const float*)d_in[0];
    const int*   targets = (const int*)d_in[1];
    const int*   in_len  = (const int*)d_in[2];
    const int*   tgt_len = (const int*)d_in[3];
    float* out = (float*)d_out;

    int T = in_sizes[0] / (BB * NC);   // 600

    // 560 warps = 140 blocks x 4 warps: 1 packed warp per SMSP on 140 SMs
    ctc_fwd<<<NW / 4, 128>>>(logits, targets, in_len, tgt_len, T, out);
}

// round 11
// speedup vs baseline: 1.0596x; 1.0596x over previous
#include <cuda_runtime.h>

#define BB 32
#define FF 35
#define SS 80
#define NC (2*FF+1)          // 71
#define NPAIR (BB*FF)        // 1120 chains
#define NW (NPAIR/2)         // 560 warps, 2 independent scalar chains each
#define LN2F 0.69314718055994530942f

__device__ float g_loss[NPAIR];
__device__ unsigned g_count = 0;

__device__ __forceinline__ float frcp(float x) {
    float r; asm("rcp.approx.f32 %0, %1;" : "=f"(r) : "f"(x)); return r;
}

// mantissa-normalize into [1,2), accumulate exponent
#define EXTR(Z, ez) { int _bt = __float_as_int(Z); ez += (_bt >> 23) - 127; \
                      Z = __int_as_float((_bt & 0x7fffff) | 0x3f800000); }

__global__ __launch_bounds__(128, 1)
void ctc_fwd(const float* __restrict__ logits,
             const int*   __restrict__ targets,
             const int*   __restrict__ in_len,
             const int*   __restrict__ tgt_len,
             int T, float* __restrict__ out)
{
    __shared__ float4 sEE[4][32];     // per step: (e0'A, e1'A, e0'B, e1'B)
    __shared__ float  sred[128];
    __shared__ int    sflag;

    const unsigned FM = 0xffffffffu;
    const int widb = threadIdx.x >> 5;
    const int lane = threadIdx.x & 31;
    const int gw = blockIdx.x * 4 + widb;      // 0..559

    const int cA = gw * 2, cB = cA + 1;
    const int bA = cA / FF, fA = cA - bA * FF;
    const int bB = cB / FF, fB = cB - bB * FF;
    const int tlA = tgt_len[cA], tlB = tgt_len[cB];
    const int LvA = 2 * tlA + 1, LvB = 2 * tlB + 1;
    int TinA = in_len[bA]; if (TinA > T) TinA = T;
    int TinB = in_len[bB]; if (TinB > T) TinB = T;
    const int Tmin = (TinA < TinB) ? TinA : TinB;
    const int Tmax = (TinA > TinB) ? TinA : TinB;

    const int l0 = lane * 6;
    const int* tgA = targets + (size_t)cA * SS;
    const int* tgB = targets + (size_t)cB * SS;

    // per-lane static constants, per chain (suffix A / B)
    #define MKCONST(S, Lv, tg) \
        const float M0##S = (l0 + 0 < Lv) ? 1.f : 0.f; \
        const float M1##S = (l0 + 1 < Lv) ? 1.f : 0.f; \
        const float M2##S = (l0 + 2 < Lv) ? 1.f : 0.f; \
        const float M3##S = (l0 + 3 < Lv) ? 1.f : 0.f; \
        const float M4##S = (l0 + 4 < Lv) ? 1.f : 0.f; \
        const float M5##S = (l0 + 5 < Lv) ? 1.f : 0.f; \
        bool  w1##S = false, w3##S = false, w5##S = false; \
        float sk1##S = 0.f, sk3##S = 0.f, sk5##S = 0.f; \
        { int l = l0 + 1; \
          if (l < Lv) { int s = (l - 1) >> 1; int tv = tg[s]; \
              w1##S = (tv != 0); sk1##S = (l >= 3 && tg[s-1] != tv) ? 1.f : 0.f; } \
          l = l0 + 3; \
          if (l < Lv) { int s = (l - 1) >> 1; int tv = tg[s]; \
              w3##S = (tv != 0); sk3##S = (l >= 3 && tg[s-1] != tv) ? 1.f : 0.f; } \
          l = l0 + 5; \
          if (l < Lv) { int s = (l - 1) >> 1; int tv = tg[s]; \
              w5##S = (tv != 0); sk5##S = (l >= 3 && tg[s-1] != tv) ? 1.f : 0.f; } }
    MKCONST(A, LvA, tgA)
    MKCONST(B, LvB, tgB)
    #undef MKCONST

    const float* pA = logits + (size_t)bA * NC + fA;
    const float* pB = logits + (size_t)bB * NC + fB;
    const int oblA = 2 * FF - fA;
    const int oblB = 2 * FF - fB;
    const int TS = BB * NC;

    float A0A = 0.f, A1A = 0.f, A2A = 0.f, A3A = 0.f, A4A = 0.f, A5A = 0.f, a5pA = 0.f;
    float A0B = 0.f, A1B = 0.f, A2B = 0.f, A3B = 0.f, A4B = 0.f, A5B = 0.f, a5pB = 0.f;
    float ZaccA = 1.f, PaccA = 1.f, ZaccB = 1.f, PaccB = 1.f;
    int ezA = 0, epA = 0, EA = 0, ezB = 0, epB = 0, EB = 0;

    // ---- t = 0 init (full emissions; Z(0) into lane-0 accumulators) ----
    {
        float e0a = __expf(pA[0]), e1a = __expf(pA[FF]), e2a = __expf(pA[oblA]);
        float e0b = __expf(pB[0]), e1b = __expf(pB[FF]), e2b = __expf(pB[oblB]);
        if (lane == 0) {
            A0A = e2a; A1A = (w1A ? e1a : e0a) * M1A; ZaccA = e0a + e1a + e2a;
            A0B = e2b; A1B = (w1B ? e1b : e0b) * M1B; ZaccB = e0b + e1b + e2b;
        }
    }

    // ---- prefetch first block (t = 1 + lane) ----
    float rpA = 0.f, rnA = 0.f, rbA = 0.f, rpB = 0.f, rnB = 0.f, rbB = 0.f;
    {
        int tt = 1 + lane;
        if (tt < Tmax) {
            const float* qa = pA + (size_t)tt * TS;
            rpA = qa[0]; rnA = qa[FF]; rbA = qa[oblA];
            const float* qb = pB + (size_t)tt * TS;
            rpB = qb[0]; rnB = qb[FF]; rbB = qb[oblB];
        }
    }

// one scalar CTC step for chain S from blank-factored emissions (e0', e1')
#define STEPX(S, e0v, e1v) { \
    float t1v = w1##S ? e1v : e0v; \
    float t3v = w3##S ? e1v : e0v; \
    float t5v = w5##S ? e1v : e0v; \
    float n5 = fmaf(sk5##S, A3##S, A5##S + A4##S) * t5v; \
    float n1 = fmaf(sk1##S, a5p##S, A1##S + A0##S) * t1v; \
    float n3 = fmaf(sk3##S, A1##S, A3##S + A2##S) * t3v; \
    float n0 = A0##S + a5p##S; \
    float n2 = A2##S + A1##S; \
    float n4 = A4##S + A3##S; \
    A0##S = n0; A1##S = n1; A2##S = n2; A3##S = n3; A4##S = n4; A5##S = n5; \
    float sh##S = __shfl_up_sync(FM, A5##S, 1); \
    a5p##S = lane ? sh##S : 0.f; }

// exact power-of-2 rescale for chain S; masks zero junk states; a5p refreshed
#define APPLYX(S, sv) { \
    int ex = (__float_as_int(sv) >> 23) & 0xff; \
    ex = min(max(ex, 1), 253); \
    E##S += ex - 127; \
    float sc = __int_as_float((254 - ex) << 23); \
    A0##S *= sc * M0##S; A1##S *= sc * M1##S; A2##S *= sc * M2##S; \
    A3##S *= sc * M3##S; A4##S *= sc * M4##S; A5##S *= sc * M5##S; \
    float sh##S = __shfl_up_sync(FM, A5##S, 1); \
    a5p##S = lane ? sh##S : 0.f; }

    for (int tb = 1; tb < Tmax; tb += 32) {
        int ns = Tmax - tb; if (ns > 32) ns = 32;

        // ---- stage blank-factored emissions; accumulate Z and blank product P ----
        float e0a = __expf(rpA), e1a = __expf(rnA), e2a = __expf(rbA);
        float e0b = __expf(rpB), e1b = __expf(rnB), e2b = __expf(rbB);
        float r2a = frcp(e2a), r2b = frcp(e2b);
        __syncwarp();
        sEE[widb][lane] = make_float4(e0a * r2a, e1a * r2a, e0b * r2b, e1b * r2b);
        int tt = tb + lane;
        if (tt < TinA) { ZaccA *= (e0a + e1a + e2a); EXTR(ZaccA, ezA);
                         PaccA *= e2a;               EXTR(PaccA, epA); }
        if (tt < TinB) { ZaccB *= (e0b + e1b + e2b); EXTR(ZaccB, ezB);
                         PaccB *= e2b;               EXTR(PaccB, epB); }

        // prefetch next block
        int tn = tb + 32 + lane;
        if (tn < Tmax) {
            const float* qa = pA + (size_t)tn * TS;
            rpA = qa[0]; rnA = qa[FF]; rbA = qa[oblA];
            const float* qb = pB + (size_t)tn * TS;
            rpB = qb[0]; rnB = qb[FF]; rbB = qb[oblB];
        }
        __syncwarp();

        if (tb + 32 <= Tmin) {
            // fast path: both chains active all 32 steps; LDS pipelined one
            // step ahead; rescale every 16 steps, butterflies spread over
            // steps 11..15 / 27..31 (independent A/B reductions give ILP)
            float svA = 0.f, svB = 0.f;
            float4 ep = sEE[widb][0];
            #pragma unroll
            for (int i = 0; i < 32; i++) {
                float4 epn;
                if (i < 31) epn = sEE[widb][i + 1];
                STEPX(A, ep.x, ep.y)
                STEPX(B, ep.z, ep.w)
                if (i < 31) ep = epn;
                if (i == 10 || i == 26) {
                    svA = ((A0A + A1A) + (A2A + A3A)) + (A4A + A5A);
                    svB = ((A0B + A1B) + (A2B + A3B)) + (A4B + A5B);
                }
                if (i == 11 || i == 27) { svA += __shfl_xor_sync(FM, svA, 1);
                                          svB += __shfl_xor_sync(FM, svB, 1); }
                if (i == 12 || i == 28) { svA += __shfl_xor_sync(FM, svA, 2);
                                          svB += __shfl_xor_sync(FM, svB, 2); }
                if (i == 13 || i == 29) { svA += __shfl_xor_sync(FM, svA, 4);
                                          svB += __shfl_xor_sync(FM, svB, 4); }
                if (i == 14 || i == 30) { svA += __shfl_xor_sync(FM, svA, 8);
                                          svB += __shfl_xor_sync(FM, svB, 8); }
                if (i == 15 || i == 31) {
                    svA += __shfl_xor_sync(FM, svA, 16);
                    svB += __shfl_xor_sync(FM, svB, 16);
                    APPLYX(A, svA)
                    APPLYX(B, svB)
                }
            }
        } else {
            // tail / unequal-length path: warp-uniform per-chain guards
            for (int i = 0; i < ns; i++) {
                int t = tb + i;
                float4 ep = sEE[widb][i];
                if (t < TinA) STEPX(A, ep.x, ep.y)
                if (t < TinB) STEPX(B, ep.z, ep.w)
                if ((i & 7) == 7) {
                    float svA = ((A0A + A1A) + (A2A + A3A)) + (A4A + A5A);
                    float svB = ((A0B + A1B) + (A2B + A3B)) + (A4B + A5B);
                    #pragma unroll
                    for (int o = 16; o; o >>= 1) {
                        svA += __shfl_xor_sync(FM, svA, o);
                        svB += __shfl_xor_sync(FM, svB, o);
                    }
                    // rescale is value-preserving (scale + exponent), so it is
                    // harmless on a frozen chain
                    APPLYX(A, svA)
                    APPLYX(B, svB)
                }
            }
        }
    }

    // ---- final gather: alpha[2*tl] + alpha[2*tl-1] per chain ----
    float lastA = 0.f, prvA = 0.f, lastB = 0.f, prvB = 0.f;
    {
        int ilA = 2 * tlA, ilB = 2 * tlB;
        #define GATH(j, RA, RB) { int l = l0 + j; \
            if (l == ilA) lastA = RA; if (l == ilA - 1) prvA = RA; \
            if (l == ilB) lastB = RB; if (l == ilB - 1) prvB = RB; }
        GATH(0, A0A, A0B) GATH(1, A1A, A1B) GATH(2, A2A, A2B)
        GATH(3, A3A, A3B) GATH(4, A4A, A4B) GATH(5, A5A, A5B)
        #undef GATH
    }
    float fsA = lastA + prvA, fsB = lastB + prvB;
    float lzA = __logf(ZaccA) - __logf(PaccA) + (float)(ezA - epA) * LN2F;
    float lzB = __logf(ZaccB) - __logf(PaccB) + (float)(ezB - epB) * LN2F;
    #pragma unroll
    for (int o = 16; o; o >>= 1) {
        fsA += __shfl_xor_sync(FM, fsA, o);
        fsB += __shfl_xor_sync(FM, fsB, o);
        lzA += __shfl_xor_sync(FM, lzA, o);
        lzB += __shfl_xor_sync(FM, lzB, o);
    }
    if (lane == 0) {
        float lossA = 0.f, lossB = 0.f;
        if (fsA > 0.f) lossA = lzA - (__logf(fsA) + (float)EA * LN2F);
        if (fsB > 0.f) lossB = lzB - (__logf(fsB) + (float)EB * LN2F);
        g_loss[cA] = lossA / fmaxf((float)tlA, 1.f);
        g_loss[cB] = lossB / fmaxf((float)tlB, 1.f);
    }

    // ---- fused grid reduction: last-arriving block sums g_loss ----
    __syncthreads();
    if (threadIdx.x == 0) {
        __threadfence();
        unsigned v = atomicAdd(&g_count, 1u);
        sflag = (v == gridDim.x - 1u) ? 1 : 0;
    }
    __syncthreads();
    if (sflag) {
        __threadfence();
        float acc = 0.f;
        for (int i = threadIdx.x; i < NPAIR; i += 128) acc += g_loss[i];
        sred[threadIdx.x] = acc;
        __syncthreads();
        #pragma unroll
        for (int o = 64; o; o >>= 1) {
            if (threadIdx.x < o) sred[threadIdx.x] += sred[threadIdx.x + o];
            __syncthreads();
        }
        if (threadIdx.x == 0) {
            out[0] = sred[0] * (1.0f / (float)BB);
            g_count = 0;
            __threadfence();
        }
    }
}

extern "C" void kernel_launch(void* const* d_in, const int* in_sizes, int n_in,
                              void* d_out, int out_size)
{
    const float* logits  = (const float*)d_in[0];
    const int*   targets = (const int*)d_in[1];
    const int*   in_len  = (const int*)d_in[2];
    const int*   tgt_len = (const int*)d_in[3];
    float* out = (float*)d_out;

    int T = in_sizes[0] / (BB * NC);   // 600

    // 560 warps = 140 blocks x 4 warps; each warp runs 2 independent scalar
    // chains interleaved (ILP fills shfl/LDS latency within the warp)
    ctc_fwd<<<NW / 4, 128>>>(logits, targets, in_len, tgt_len, T, out);
}

// round 12
// speedup vs baseline: 1.1763x; 1.1102x over previous
#include <cuda_runtime.h>

#define BB 32
#define FF 35
#define SS 80
#define NC (2*FF+1)          // 71
#define NPAIR (BB*FF)        // 1120 chains
#define NW (NPAIR/2)         // 560 warps; each warp = 2 chains in lane halves
#define LN2F 0.69314718055994530942f

__device__ float g_loss[NPAIR];
__device__ unsigned g_count = 0;

__device__ __forceinline__ float frcp(float x) {
    float r; asm("rcp.approx.f32 %0, %1;" : "=f"(r) : "f"(x)); return r;
}

// mantissa-normalize into [1,2), accumulate exponent
#define EXTR(Z, ez) { int _bt = __float_as_int(Z); ez += (_bt >> 23) - 127; \
                      Z = __int_as_float((_bt & 0x7fffff) | 0x3f800000); }

__global__ __launch_bounds__(128, 1)
void ctc_fwd(const float* __restrict__ logits,
             const int*   __restrict__ targets,
             const int*   __restrict__ in_len,
             const int*   __restrict__ tgt_len,
             int T, float* __restrict__ out)
{
    __shared__ float4 sEE[4][32];     // per step: (e0'A, e1'A, e0'B, e1'B)
    __shared__ float  sred[128];
    __shared__ int    sflag;

    const unsigned FM = 0xffffffffu;
    const int widb = threadIdx.x >> 5;
    const int lane = threadIdx.x & 31;
    const int gw = blockIdx.x * 4 + widb;      // 0..559

    const int cA = gw * 2, cB = cA + 1;
    const int bA = cA / FF, fA = cA - bA * FF;
    const int bB = cB / FF, fB = cB - bB * FF;
    const int tlA = tgt_len[cA], tlB = tgt_len[cB];
    int TinA = in_len[bA]; if (TinA > T) TinA = T;
    int TinB = in_len[bB]; if (TinB > T) TinB = T;
    const int Tmin = (TinA < TinB) ? TinA : TinB;
    const int Tmax = (TinA > TinB) ? TinA : TinB;

    // lane-half mapping: lanes 0-15 = chain A, lanes 16-31 = chain B
    const int grp  = lane >> 4;
    const int lidx = lane & 15;
    const int cX   = grp ? cB : cA;
    const int tlX  = grp ? tlB : tlA;
    const int LvX  = 2 * tlX + 1;
    const int TinX = grp ? TinB : TinA;
    const int l0   = lidx * 12;               // 12 states per lane
    const int* tg  = targets + (size_t)cX * SS;

    // masks (APPLY-time junk containment)
    #define MKM(j) const float Ms##j = (l0 + j < LvX) ? 1.f : 0.f;
    MKM(0) MKM(1) MKM(2) MKM(3) MKM(4) MKM(5)
    MKM(6) MKM(7) MKM(8) MKM(9) MKM(10) MKM(11)
    #undef MKM
    // odd-state statics: label bit + skip coefficient
    #define MKODD(j, wj, skj) bool wj = false; float skj = 0.f; \
        { int l = l0 + j; \
          if (l < LvX) { int s = (l - 1) >> 1; int tv = tg[s]; \
              wj = (tv != 0); skj = (l >= 3 && tg[s - 1] != tv) ? 1.f : 0.f; } }
    MKODD(1,  w1,  sk1)  MKODD(3,  w3,  sk3)  MKODD(5,  w5,  sk5)
    MKODD(7,  w7,  sk7)  MKODD(9,  w9,  sk9)  MKODD(11, w11, sk11)
    #undef MKODD
    const float bm = (lidx == 0) ? 0.f : 1.f;   // kills boundary into group starts

    const float* pA = logits + (size_t)bA * NC + fA;
    const float* pB = logits + (size_t)bB * NC + fB;
    const int oblA = 2 * FF - fA;
    const int oblB = 2 * FF - fB;
    const int TS = BB * NC;

    float A0=0.f,A1=0.f,A2=0.f,A3=0.f,A4=0.f,A5=0.f,
          A6=0.f,A7=0.f,A8=0.f,A9=0.f,A10=0.f,A11=0.f;
    float bp = 0.f;                       // prev-lane A11 (shuffled 1 step early)
    float ZaccA = 1.f, PaccA = 1.f, ZaccB = 1.f, PaccB = 1.f;
    int ezA = 0, epA = 0, ezB = 0, epB = 0, E = 0;

    // ---- t = 0 init (full emissions; Z(0) into lane-0 accumulators) ----
    {
        float e0a = __expf(pA[0]), e1a = __expf(pA[FF]), e2a = __expf(pA[oblA]);
        float e0b = __expf(pB[0]), e1b = __expf(pB[FF]), e2b = __expf(pB[oblB]);
        if (lane == 0) {
            A0 = e2a; A1 = (w1 ? e1a : e0a) * Ms1;      // lane0 statics = chain A
            ZaccA = e0a + e1a + e2a;
            ZaccB = e0b + e1b + e2b;
        }
        if (lane == 16) {
            A0 = e2b; A1 = (w1 ? e1b : e0b) * Ms1;      // lane16 statics = chain B
        }
    }

    // ---- prefetch first block (t = 1 + lane) ----
    float rpA = 0.f, rnA = 0.f, rbA = 0.f, rpB = 0.f, rnB = 0.f, rbB = 0.f;
    {
        int tt = 1 + lane;
        if (tt < Tmax) {
            const float* qa = pA + (size_t)tt * TS;
            rpA = qa[0]; rnA = qa[FF]; rbA = qa[oblA];
            const float* qb = pB + (size_t)tt * TS;
            rpB = qb[0]; rnB = qb[FF]; rbB = qb[oblB];
        }
    }

// one CTC step, 12 states, both chains (lane halves). n11 computed FIRST and
// its shuffle issued immediately; bp (consumed at the END via n1/n0) is the
// shuffle from the PREVIOUS step -> ~full step of slack on both sides.
#define STEPX(e0q, e1q) { \
    float t11v = w11 ? e1q : e0q; \
    float n11 = fmaf(sk11, A9, A11 + A10) * t11v; \
    float shv = __shfl_up_sync(FM, n11, 1); \
    float t1v = w1 ? e1q : e0q; \
    float t3v = w3 ? e1q : e0q; \
    float t5v = w5 ? e1q : e0q; \
    float t7v = w7 ? e1q : e0q; \
    float t9v = w9 ? e1q : e0q; \
    float n3 = fmaf(sk3, A1, A3 + A2) * t3v; \
    float n5 = fmaf(sk5, A3, A5 + A4) * t5v; \
    float n7 = fmaf(sk7, A5, A7 + A6) * t7v; \
    float n9 = fmaf(sk9, A7, A9 + A8) * t9v; \
    float n2 = A2 + A1;  float n4 = A4 + A3;  float n6 = A6 + A5; \
    float n8 = A8 + A7;  float n10 = A10 + A9; \
    float n1 = fmaf(sk1, bp, A1 + A0) * t1v; \
    float n0 = fmaf(bm, bp, A0); \
    A0=n0; A1=n1; A2=n2; A3=n3; A4=n4; A5=n5; \
    A6=n6; A7=n7; A8=n8; A9=n9; A10=n10; A11=n11; \
    bp = shv; }

#define SUMALL ((((A0+A1)+(A2+A3))+((A4+A5)+(A6+A7)))+((A8+A9)+(A10+A11)))

// exact power-of-2 rescale (per 16-lane group); masks zero junk states; bp rescaled
#define APPLYX(sv) { \
    int ex = (__float_as_int(sv) >> 23) & 0xff; \
    ex = min(max(ex, 1), 253); \
    E += ex - 127; \
    float sc = __int_as_float((254 - ex) << 23); \
    A0  *= sc * Ms0;  A1  *= sc * Ms1;  A2  *= sc * Ms2;  A3  *= sc * Ms3; \
    A4  *= sc * Ms4;  A5  *= sc * Ms5;  A6  *= sc * Ms6;  A7  *= sc * Ms7; \
    A8  *= sc * Ms8;  A9  *= sc * Ms9;  A10 *= sc * Ms10; A11 *= sc * Ms11; \
    bp *= sc; }

    for (int tb = 1; tb < Tmax; tb += 32) {
        int ns = Tmax - tb; if (ns > 32) ns = 32;

        // ---- stage blank-factored emissions; accumulate Z and blank product P ----
        float e0a = __expf(rpA), e1a = __expf(rnA), e2a = __expf(rbA);
        float e0b = __expf(rpB), e1b = __expf(rnB), e2b = __expf(rbB);
        float r2a = frcp(e2a), r2b = frcp(e2b);
        __syncwarp();
        sEE[widb][lane] = make_float4(e0a * r2a, e1a * r2a, e0b * r2b, e1b * r2b);
        int tt = tb + lane;
        if (tt < TinA) { ZaccA *= (e0a + e1a + e2a); EXTR(ZaccA, ezA);
                         PaccA *= e2a;               EXTR(PaccA, epA); }
        if (tt < TinB) { ZaccB *= (e0b + e1b + e2b); EXTR(ZaccB, ezB);
                         PaccB *= e2b;               EXTR(PaccB, epB); }

        // prefetch next block
        int tn = tb + 32 + lane;
        if (tn < Tmax) {
            const float* qa = pA + (size_t)tn * TS;
            rpA = qa[0]; rnA = qa[FF]; rbA = qa[oblA];
            const float* qb = pB + (size_t)tn * TS;
            rpB = qb[0]; rnB = qb[FF]; rbB = qb[oblB];
        }
        __syncwarp();

        if (tb + 32 <= Tmin) {
            // fast path: both chains active; LDS pipelined one step ahead;
            // rescale every 16 steps, 4-hop group butterfly spread over
            // steps 12..15 / 28..31
            float sv = 0.f;
            float4 ep = sEE[widb][0];
            #pragma unroll
            for (int i = 0; i < 32; i++) {
                float4 epn;
                if (i < 31) epn = sEE[widb][i + 1];
                float e0q = grp ? ep.z : ep.x;
                float e1q = grp ? ep.w : ep.y;
                STEPX(e0q, e1q)
                if (i < 31) ep = epn;
                if (i == 11 || i == 27) sv = SUMALL;
                if (i == 12 || i == 28) sv += __shfl_xor_sync(FM, sv, 8);
                if (i == 13 || i == 29) sv += __shfl_xor_sync(FM, sv, 4);
                if (i == 14 || i == 30) sv += __shfl_xor_sync(FM, sv, 2);
                if (i == 15 || i == 31) {
                    sv += __shfl_xor_sync(FM, sv, 1);
                    APPLYX(sv)
                }
            }
        } else {
            // tail / unequal-length path: per-lane freeze via selects;
            // boundary re-shuffled from committed state
            for (int i = 0; i < ns; i++) {
                int t = tb + i;
                float4 ep = sEE[widb][i];
                float e0q = grp ? ep.z : ep.x;
                float e1q = grp ? ep.w : ep.y;
                float t11v = w11 ? e1q : e0q;
                float t1v = w1 ? e1q : e0q;
                float t3v = w3 ? e1q : e0q;
                float t5v = w5 ? e1q : e0q;
                float t7v = w7 ? e1q : e0q;
                float t9v = w9 ? e1q : e0q;
                float n11 = fmaf(sk11, A9, A11 + A10) * t11v;
                float n3 = fmaf(sk3, A1, A3 + A2) * t3v;
                float n5 = fmaf(sk5, A3, A5 + A4) * t5v;
                float n7 = fmaf(sk7, A5, A7 + A6) * t7v;
                float n9 = fmaf(sk9, A7, A9 + A8) * t9v;
                float n2 = A2 + A1;  float n4 = A4 + A3;  float n6 = A6 + A5;
                float n8 = A8 + A7;  float n10 = A10 + A9;
                float n1 = fmaf(sk1, bp, A1 + A0) * t1v;
                float n0 = fmaf(bm, bp, A0);
                bool g = (t < TinX);
                A0 = g ? n0 : A0;   A1 = g ? n1 : A1;   A2 = g ? n2 : A2;
                A3 = g ? n3 : A3;   A4 = g ? n4 : A4;   A5 = g ? n5 : A5;
                A6 = g ? n6 : A6;   A7 = g ? n7 : A7;   A8 = g ? n8 : A8;
                A9 = g ? n9 : A9;   A10 = g ? n10 : A10; A11 = g ? n11 : A11;
                bp = __shfl_up_sync(FM, A11, 1);
                if ((i & 15) == 15) {
                    float sv = SUMALL;
                    sv += __shfl_xor_sync(FM, sv, 8);
                    sv += __shfl_xor_sync(FM, sv, 4);
                    sv += __shfl_xor_sync(FM, sv, 2);
                    sv += __shfl_xor_sync(FM, sv, 1);
                    APPLYX(sv)
                }
            }
        }
    }

    // ---- final gather: alpha[2*tl] + alpha[2*tl-1], per lane-half chain ----
    float last = 0.f, prv = 0.f;
    {
        int il = 2 * tlX;
        #define GATH(j, R) { int l = l0 + j; \
            if (l == il) last = R; if (l == il - 1) prv = R; }
        GATH(0, A0) GATH(1, A1) GATH(2, A2)  GATH(3, A3)  GATH(4, A4)   GATH(5, A5)
        GATH(6, A6) GATH(7, A7) GATH(8, A8)  GATH(9, A9)  GATH(10, A10) GATH(11, A11)
        #undef GATH
    }
    float fs = last + prv;                 // group-local reduction (4 hops)
    fs += __shfl_xor_sync(FM, fs, 8);
    fs += __shfl_xor_sync(FM, fs, 4);
    fs += __shfl_xor_sync(FM, fs, 2);
    fs += __shfl_xor_sync(FM, fs, 1);
    // Z/P contributions live on all 32 lanes for both chains: full butterfly
    float lzA = __logf(ZaccA) - __logf(PaccA) + (float)(ezA - epA) * LN2F;
    float lzB = __logf(ZaccB) - __logf(PaccB) + (float)(ezB - epB) * LN2F;
    #pragma unroll
    for (int o = 16; o; o >>= 1) {
        lzA += __shfl_xor_sync(FM, lzA, o);
        lzB += __shfl_xor_sync(FM, lzB, o);
    }
    if (lidx == 0) {                        // lanes 0 and 16 write their chain
        float lzX = grp ? lzB : lzA;
        float lossv = 0.f;
        if (fs > 0.f) lossv = lzX - (__logf(fs) + (float)E * LN2F);
        g_loss[cX] = lossv / fmaxf((float)tlX, 1.f);
    }

    // ---- fused grid reduction: last-arriving block sums g_loss ----
    __syncthreads();
    if (threadIdx.x == 0) {
        __threadfence();
        unsigned v = atomicAdd(&g_count, 1u);
        sflag = (v == gridDim.x - 1u) ? 1 : 0;
    }
    __syncthreads();
    if (sflag) {
        __threadfence();
        float acc = 0.f;
        for (int i = threadIdx.x; i < NPAIR; i += 128) acc += g_loss[i];
        sred[threadIdx.x] = acc;
        __syncthreads();
        #pragma unroll
        for (int o = 64; o; o >>= 1) {
            if (threadIdx.x < o) sred[threadIdx.x] += sred[threadIdx.x + o];
            __syncthreads();
        }
        if (threadIdx.x == 0) {
            out[0] = sred[0] * (1.0f / (float)BB);
            g_count = 0;
            __threadfence();
        }
    }
}

extern "C" void kernel_launch(void* const* d_in, const int* in_sizes, int n_in,
                              void* d_out, int out_size)
{
    const float* logits  = (const float*)d_in[0];
    const int*   targets = (const int*)d_in[1];
    const int*   in_len  = (const int*)d_in[2];
    const int*   tgt_len = (const int*)d_in[3];
    float* out = (float*)d_out;

    int T = in_sizes[0] / (BB * NC);   // 600

    // 560 warps = 140 blocks x 4 warps; each warp = 2 chains in lane halves
    // (12 states/lane): one shfl/step for BOTH chains, 12-way intra-step ILP
    ctc_fwd<<<NW / 4, 128>>>(logits, targets, in_len, tgt_len, T, out);
}

// round 14
// speedup vs baseline: 1.2425x; 1.0563x over previous
#include <cuda_runtime.h>

#define BB 32
#define FF 35
#define SS 80
#define NC (2*FF+1)          // 71
#define NPAIR (BB*FF)        // 1120 chains, 1 chain per warp
#define WPB 8                // 8 warps per block -> 2 per SMSP
#define NB (NPAIR/WPB)       // 140 blocks
#define LN2F 0.69314718055994530942f

__device__ float g_loss[NPAIR];
__device__ unsigned g_count = 0;

__device__ __forceinline__ float frcp(float x) {
    float r; asm("rcp.approx.f32 %0, %1;" : "=f"(r) : "f"(x)); return r;
}

// mantissa-normalize into [1,2), accumulate exponent
#define EXTR(Z, ez) { int _bt = __float_as_int(Z); ez += (_bt >> 23) - 127; \
                      Z = __int_as_float((_bt & 0x7fffff) | 0x3f800000); }

__global__ __launch_bounds__(256, 1)
void ctc_fwd(const float* __restrict__ logits,
             const int*   __restrict__ targets,
             const int*   __restrict__ in_len,
             const int*   __restrict__ tgt_len,
             int T, float* __restrict__ out)
{
    __shared__ float2 sEE[WPB][32];    // per step: (e0', e1') blank-factored
    __shared__ float  sred[256];
    __shared__ int    sflag;

    const unsigned FM = 0xffffffffu;
    const int widb = threadIdx.x >> 5;
    const int lane = threadIdx.x & 31;
    const int c = blockIdx.x * WPB + widb;    // chain 0..1119

    const int b = c / FF, f = c - b * FF;
    const int tl = tgt_len[c];
    const int Lv = 2 * tl + 1;
    int Tin = in_len[b]; if (Tin > T) Tin = T;

    const int l0 = lane * 6;
    const int* tg = targets + (size_t)c * SS;

    // per-lane static constants
    const float M0 = (l0 + 0 < Lv) ? 1.f : 0.f;
    const float M1 = (l0 + 1 < Lv) ? 1.f : 0.f;
    const float M2 = (l0 + 2 < Lv) ? 1.f : 0.f;
    const float M3 = (l0 + 3 < Lv) ? 1.f : 0.f;
    const float M4 = (l0 + 4 < Lv) ? 1.f : 0.f;
    const float M5 = (l0 + 5 < Lv) ? 1.f : 0.f;
    bool  w1 = false, w3 = false, w5 = false;
    float sk1 = 0.f, sk3 = 0.f, sk5 = 0.f;
    {
        int l = l0 + 1;
        if (l < Lv) { int s = (l - 1) >> 1; int tv = tg[s];
            w1 = (tv != 0); sk1 = (l >= 3 && tg[s - 1] != tv) ? 1.f : 0.f; }
        l = l0 + 3;
        if (l < Lv) { int s = (l - 1) >> 1; int tv = tg[s];
            w3 = (tv != 0); sk3 = (l >= 3 && tg[s - 1] != tv) ? 1.f : 0.f; }
        l = l0 + 5;
        if (l < Lv) { int s = (l - 1) >> 1; int tv = tg[s];
            w5 = (tv != 0); sk5 = (l >= 3 && tg[s - 1] != tv) ? 1.f : 0.f; }
    }
    // NOTE: on lane 0, sk1 == 0 (l=1 is never >= 3) and lzm == 0, so the
    // garbage value shfl_up delivers to lane 0 is annihilated without a select.
    const float lzm = lane ? 1.f : 0.f;

    const float* pC = logits + (size_t)b * NC + f;   // chain's pos channel, t=0
    const int obl = 2 * FF - f;                      // pos -> blank offset
    const int TS = BB * NC;

    float A0 = 0.f, A1 = 0.f, A2 = 0.f, A3 = 0.f, A4 = 0.f, A5 = 0.f, a5p = 0.f;
    float Zacc = 1.f, Pacc = 1.f;
    int ez = 0, ep_ = 0, E = 0;

    // ---- t = 0 init (full emissions; Z(0) folded into lane-0 Zacc) ----
    {
        float e0 = __expf(pC[0]), e1 = __expf(pC[FF]), e2 = __expf(pC[obl]);
        if (lane == 0) {
            A0 = e2;
            A1 = (w1 ? e1 : e0) * M1;
            Zacc = e0 + e1 + e2;
        }
    }

    // ---- prefetch first block (t = 1 + lane) ----
    float rp = 0.f, rn = 0.f, rb = 0.f;
    {
        int tt = 1 + lane;
        if (tt < Tin) {
            const float* q = pC + (size_t)tt * TS;
            rp = q[0]; rn = q[FF]; rb = q[obl];
        }
    }

// one CTC step. n5 computed FIRST and its shuffle issued immediately; the
// consumers of the incoming a5p (n1, n0) are computed LAST, so the shuffle
// has ~a full step of slack on both the produce and consume side.
#define STEP_EP(e0v, e1v) { \
    float t5v = w5 ? e1v : e0v; \
    float n5 = fmaf(sk5, A3, A5 + A4) * t5v; \
    float shv = __shfl_up_sync(FM, n5, 1); \
    float t1v = w1 ? e1v : e0v; \
    float t3v = w3 ? e1v : e0v; \
    float n3 = fmaf(sk3, A1, A3 + A2) * t3v; \
    float n2 = A2 + A1; \
    float n4 = A4 + A3; \
    float n1 = fmaf(sk1, a5p, A1 + A0) * t1v; \
    float n0 = fmaf(lzm, a5p, A0); \
    A0 = n0; A1 = n1; A2 = n2; A3 = n3; A4 = n4; A5 = n5; \
    a5p = shv; }

// exact power-of-2 rescale from reduced sum sv; masks zero junk states; a5p
// refreshed from the masked A5 (lane-0 garbage killed by sk1/lzm zeros)
#define APPLY(sv) { \
    int ex = (__float_as_int(sv) >> 23) & 0xff; \
    ex = min(max(ex, 1), 253); \
    E += ex - 127; \
    float sc = __int_as_float((254 - ex) << 23); \
    A0 = A0 * (sc * M0); A1 = A1 * (sc * M1); A2 = A2 * (sc * M2); \
    A3 = A3 * (sc * M3); A4 = A4 * (sc * M4); A5 = A5 * (sc * M5); \
    a5p = __shfl_up_sync(FM, A5, 1); }

    for (int tb = 1; tb < Tin; tb += 32) {
        int ns = Tin - tb; if (ns > 32) ns = 32;

        // ---- stage blank-factored emissions; accumulate Z and blank product P ----
        float e0 = __expf(rp), e1 = __expf(rn), e2 = __expf(rb);
        float r2 = frcp(e2);
        __syncwarp();
        sEE[widb][lane] = make_float2(e0 * r2, e1 * r2);
        int tt = tb + lane;
        if (tt < Tin) {
            Zacc *= (e0 + e1 + e2); EXTR(Zacc, ez);
            Pacc *= e2;             EXTR(Pacc, ep_);
        }
        // prefetch next block
        int tn = tb + 32 + lane;
        if (tn < Tin) {
            const float* q = pC + (size_t)tn * TS;
            rp = q[0]; rn = q[FF]; rb = q[obl];
        }
        __syncwarp();

        if (ns == 32) {
            // fast path: LDS pipelined one step ahead;
            // rescale every 16 steps, butterfly spread over steps 11..15 / 27..31
            float sv = 0.f;
            float2 ep = sEE[widb][0];
            #pragma unroll
            for (int i = 0; i < 32; i++) {
                float2 epn;
                if (i < 31) epn = sEE[widb][i + 1];
                STEP_EP(ep.x, ep.y);
                if (i < 31) ep = epn;
                if (i == 10 || i == 26)
                    sv = ((A0 + A1) + (A2 + A3)) + (A4 + A5);
                if (i == 11 || i == 27) sv += __shfl_xor_sync(FM, sv, 1);
                if (i == 12 || i == 28) sv += __shfl_xor_sync(FM, sv, 2);
                if (i == 13 || i == 29) sv += __shfl_xor_sync(FM, sv, 4);
                if (i == 14 || i == 30) sv += __shfl_xor_sync(FM, sv, 8);
                if (i == 15 || i == 31) {
                    sv += __shfl_xor_sync(FM, sv, 16);
                    APPLY(sv);
                }
            }
        } else {
            // tail: single chain, loop just ends at Tin
            for (int i = 0; i < ns; i++) {
                float2 ep = sEE[widb][i];
                STEP_EP(ep.x, ep.y);
                if ((i & 7) == 7) {
                    float sv = ((A0 + A1) + (A2 + A3)) + (A4 + A5);
                    #pragma unroll
                    for (int o = 16; o; o >>= 1)
                        sv += __shfl_xor_sync(FM, sv, o);
                    APPLY(sv);
                }
            }
        }
    }

    // ---- final gather: alpha[2*tl] + alpha[2*tl-1] ----
    float last = 0.f, prv = 0.f;
    {
        int il = 2 * tl;
        #define GATH(j, R) { int l = l0 + j; \
            if (l == il) last = R; if (l == il - 1) prv = R; }
        GATH(0, A0) GATH(1, A1) GATH(2, A2)
        GATH(3, A3) GATH(4, A4) GATH(5, A5)
        #undef GATH
    }
    float fs = last + prv;
    float lz = __logf(Zacc) - __logf(Pacc) + (float)(ez - ep_) * LN2F;
    #pragma unroll
    for (int o = 16; o; o >>= 1) {
        fs += __shfl_xor_sync(FM, fs, o);
        lz += __shfl_xor_sync(FM, lz, o);
    }
    if (lane == 0) {
        float lossv = 0.f;
        if (fs > 0.f) lossv = lz - (__logf(fs) + (float)E * LN2F);
        g_loss[c] = lossv / fmaxf((float)tl, 1.f);
    }

    // ---- fused grid reduction: last-arriving block sums g_loss ----
    __syncthreads();
    if (threadIdx.x == 0) {
        __threadfence();
        unsigned v = atomicAdd(&g_count, 1u);
        sflag = (v == gridDim.x - 1u) ? 1 : 0;
    }
    __syncthreads();
    if (sflag) {
        __threadfence();
        float acc = 0.f;
        for (int i = threadIdx.x; i < NPAIR; i += 256) acc += g_loss[i];
        sred[threadIdx.x] = acc;
        __syncthreads();
        #pragma unroll
        for (int o = 128; o; o >>= 1) {
            if (threadIdx.x < o) sred[threadIdx.x] += sred[threadIdx.x + o];
            __syncthreads();
        }
        if (threadIdx.x == 0) {
            out[0] = sred[0] * (1.0f / (float)BB);
            g_count = 0;
            __threadfence();
        }
    }
}

extern "C" void kernel_launch(void* const* d_in, const int* in_sizes, int n_in,
                              void* d_out, int out_size)
{
    const float* logits  = (const float*)d_in[0];
    const int*   targets = (const int*)d_in[1];
    const int*   in_len  = (const int*)d_in[2];
    const int*   tgt_len = (const int*)d_in[3];
    float* out = (float*)d_out;

    int T = in_sizes[0] / (BB * NC);   // 600

    // 140 blocks x 256 threads: 1120 warps, 1 chain each, 2 warps per SMSP
    ctc_fwd<<<NB, 256>>>(logits, targets, in_len, tgt_len, T, out);
}